// round 10
// baseline (speedup 1.0000x reference)
#include <cuda_runtime.h>

// CTA-granularity bulk version: each 256-thread block owns 256 consecutive
// rows = one contiguous 25600B span. ONE cp.async.bulk load fills the
// block's smem span (all threads HW-sleep on one mbarrier); then ONE
// cp.async.bulk store streams it back out as the output (round trip is the
// identity when no reflection coefficient clips; BOUND = 1-1e-16 rounds to
// 1.0f). 8x fewer TMA ops than per-warp spans -> amortizes the ~46cyc/op
// TMA frontend cost that capped DRAM at 75%. Detector: division-free
// scaled Levinson, 1 row/thread, ~40 regs (the proven pareto point).
// Clipped rows overwrite themselves after wait_group-ordering behind the
// bulk store, gated by a block-uniform smem flag.

#define M 24
#define ROW 25
#define THREADS 256
#define ROWS_PER_BLK 256
#define FLOATS_PER_BLK (ROWS_PER_BLK * ROW)            // 6400
#define BYTES_PER_BLK  (FLOATS_PER_BLK * 4)            // 25600 (16B multiple)

__device__ __forceinline__ void mbar_wait(unsigned mb, unsigned parity)
{
    asm volatile(
        "{\n\t"
        ".reg .pred P1;\n\t"
        "LAB_WAIT%=:\n\t"
        "mbarrier.try_wait.parity.acquire.cta.shared::cta.b64 P1, [%0], %1, 0x989680;\n\t"
        "@P1 bra LAB_DONE%=;\n\t"
        "bra LAB_WAIT%=;\n\t"
        "LAB_DONE%=:\n\t"
        "}"
        :: "r"(mb), "r"(parity) : "memory");
}

// Division-free scaled downward Levinson: u_i = c_i * D, D = prod(1-k^2).
// Returns max |k_m|; > 1 (or NaN from degenerate D) means clipping fires.
__device__ __forceinline__ float detector(const float* __restrict__ row)
{
    float u[M];
    #pragma unroll
    for (int i = 0; i < M; ++i) u[i] = row[i + 1];
    float D = 1.0f, maxa = 0.0f;
    #pragma unroll
    for (int m = M; m >= 2; --m) {
        float um = u[m - 1];
        float k  = um * __fdividef(1.0f, D);
        maxa = fmaxf(maxa, fabsf(k));
        D = fmaf(-k, um, D);                 // D *= (1 - k^2)
        #pragma unroll
        for (int i = 0; 2 * i <= m - 2; ++i) {
            int j = m - 2 - i;
            float ui = u[i], uj = u[j];
            if (i < j) {
                u[i] = fmaf(-k, uj, ui);
                u[j] = fmaf(-k, ui, uj);
            } else {
                u[i] = fmaf(-k, ui, ui);
            }
        }
    }
    return fmaxf(maxa, fabsf(u[0] * __fdividef(1.0f, D)));   // k_1
}

// Exact per-row path: true divides, clamp, upward recursion, overwrite row.
__device__ __noinline__ void fixup_row(const float* __restrict__ srow,
                                       float* __restrict__ orow)
{
    float c[M];
    #pragma unroll
    for (int i = 0; i < M; ++i) c[i] = srow[i + 1];

    #pragma unroll
    for (int m = M; m >= 2; --m) {
        float k   = c[m - 1];
        float inv = __fdividef(1.0f, 1.0f - k * k);
        #pragma unroll
        for (int i = 0; 2 * i <= m - 2; ++i) {
            int j = m - 2 - i;
            float ci = c[i], cj = c[j];
            if (i < j) {
                c[i] = fmaf(-k, cj, ci) * inv;
                c[j] = fmaf(-k, ci, cj) * inv;
            } else {
                c[i] = fmaf(-k, ci, ci) * inv;
            }
        }
    }
    #pragma unroll
    for (int i = 0; i < M; ++i)
        c[i] = fminf(fmaxf(c[i], -1.0f), 1.0f);

    #pragma unroll
    for (int m = 2; m <= M; ++m) {
        float km = c[m - 1];
        #pragma unroll
        for (int i = 0; 2 * i <= m - 2; ++i) {
            int j = m - 2 - i;
            float ci = c[i], cj = c[j];
            if (i < j) {
                c[i] = fmaf(km, cj, ci);
                c[j] = fmaf(km, ci, cj);
            } else {
                c[i] = fmaf(km, ci, ci);
            }
        }
    }
    #pragma unroll
    for (int i = 0; i < M; ++i) orow[i + 1] = c[i];
    // orow[0] (gain K) already correct from the bulk copy
}

__global__ __launch_bounds__(THREADS, 6)
void lpc_stability_kernel(const float* __restrict__ in, float* __restrict__ out, int B)
{
    __shared__ float s[FLOATS_PER_BLK];                // 25.6 KB
    __shared__ unsigned long long mbar;
    __shared__ int clipflag;

    const int tid = threadIdx.x;
    const long long rbase = (long long)blockIdx.x * ROWS_PER_BLK;
    const int nrows = min((long long)ROWS_PER_BLK, B - rbase);

    const float* gsrc = in  + rbase * ROW;
    float*       gdst = out + rbase * ROW;
    unsigned s_addr = (unsigned)__cvta_generic_to_shared(s);
    unsigned mb     = (unsigned)__cvta_generic_to_shared(&mbar);

    if (nrows == ROWS_PER_BLK) {
        // ---- one async load of the block's 25600B span ----
        if (tid == 0) {
            clipflag = 0;
            asm volatile("mbarrier.init.shared.b64 [%0], %1;"
                         :: "r"(mb), "r"(1) : "memory");
            asm volatile("mbarrier.arrive.expect_tx.shared.b64 _, [%0], %1;"
                         :: "r"(mb), "r"((unsigned)BYTES_PER_BLK) : "memory");
            asm volatile("cp.async.bulk.shared::cluster.global.mbarrier::complete_tx::bytes "
                         "[%0], [%1], %2, [%3];"
                         :: "r"(s_addr), "l"(gsrc), "r"((unsigned)BYTES_PER_BLK), "r"(mb)
                         : "memory");
        }
        __syncthreads();           // init + flag visible before waits
        mbar_wait(mb, 0);          // acquire (HW-sleep): smem span ready

        // ---- one async out-copy (identity result) on the TMA engine ----
        if (tid == 0) {
            asm volatile("fence.proxy.async.shared::cta;" ::: "memory");
            asm volatile("cp.async.bulk.global.shared::cta.bulk_group [%0], [%1], %2;"
                         :: "l"(gdst), "r"(s_addr), "r"((unsigned)BYTES_PER_BLK)
                         : "memory");
            asm volatile("cp.async.bulk.commit_group;" ::: "memory");
        }

        // ---- detector (overlaps the bulk store) ----
        const float* row = s + tid * ROW;
        float maxa = detector(row);
        bool myclip = !(maxa <= 1.0f);      // catches >1 and NaN
        if (myclip) clipflag = 1;           // benign race: all write 1
        __syncthreads();                    // flag uniform across block

        if (clipflag) {                     // block-uniform rare path
            if (tid == 0)
                asm volatile("cp.async.bulk.wait_group 0;" ::: "memory");
            __syncthreads();                // fixups ordered after bulk store
            if (myclip)
                fixup_row(row, gdst + (long long)tid * ROW);
        }
    } else {
        // ---- generic tail (last block when B % 256 != 0) ----
        int nelem = nrows * ROW;
        for (int idx = tid; idx < nelem; idx += THREADS) {
            float v = gsrc[idx];
            gdst[idx] = v;
            s[idx] = v;
        }
        __syncthreads();
        if (tid < nrows) {
            const float* row = s + tid * ROW;
            if (!(detector(row) <= 1.0f))
                fixup_row(row, gdst + (long long)tid * ROW);
        }
    }
}

extern "C" void kernel_launch(void* const* d_in, const int* in_sizes, int n_in,
                              void* d_out, int out_size)
{
    const float* a = (const float*)d_in[0];
    float* out = (float*)d_out;
    int B = in_sizes[0] / ROW;
    int grid = (B + ROWS_PER_BLK - 1) / ROWS_PER_BLK;
    lpc_stability_kernel<<<grid, THREADS>>>(a, out, B);
}

// round 11
// speedup vs baseline: 1.0223x; 1.0223x over previous
#include <cuda_runtime.h>

// Warp-autonomous, 2-deep pipelined version: each warp owns 64 consecutive
// rows as TWO 3200B sub-spans with separate mbarriers. Both cp.async.bulk
// loads are issued up front; the warp then pipelines:
//   wait0 -> bulk-store0 -> detect0 (overlaps load1) -> wait1 -> store1 -> detect1
// Round trip is the identity when no reflection coefficient clips
// (BOUND = 1-1e-16 rounds to 1.0f), so the output is the bulk-stored input.
// Detector: division-free scaled Levinson, 1 row/thread, ~40 regs (the
// proven pareto point; R9's dual-chain register doubling is avoided by
// running the two chains sequentially). Clipped rows (rare to nonexistent)
// overwrite themselves after wait_group-ordering behind the bulk stores.

#define M 24
#define ROW 25
#define WARPS_PER_BLK 8
#define THREADS (WARPS_PER_BLK * 32)
#define SUB_ROWS 32
#define SUB_FLOATS (SUB_ROWS * ROW)                    // 800
#define SUB_BYTES  (SUB_FLOATS * 4)                    // 3200 (16B multiple)
#define ROWS_PER_WARP (2 * SUB_ROWS)                   // 64
#define WARP_FLOATS (2 * SUB_FLOATS)                   // 1600

__device__ __forceinline__ void mbar_wait(unsigned mb, unsigned parity)
{
    asm volatile(
        "{\n\t"
        ".reg .pred P1;\n\t"
        "LAB_WAIT%=:\n\t"
        "mbarrier.try_wait.parity.acquire.cta.shared::cta.b64 P1, [%0], %1, 0x989680;\n\t"
        "@P1 bra LAB_DONE%=;\n\t"
        "bra LAB_WAIT%=;\n\t"
        "LAB_DONE%=:\n\t"
        "}"
        :: "r"(mb), "r"(parity) : "memory");
}

// Division-free scaled downward Levinson: u_i = c_i * D, D = prod(1-k^2).
// Returns max |k_m|; > 1 (or NaN from degenerate D) means clipping fires.
__device__ __forceinline__ float detector(const float* __restrict__ row)
{
    float u[M];
    #pragma unroll
    for (int i = 0; i < M; ++i) u[i] = row[i + 1];
    float D = 1.0f, maxa = 0.0f;
    #pragma unroll
    for (int m = M; m >= 2; --m) {
        float um = u[m - 1];
        float k  = um * __fdividef(1.0f, D);
        maxa = fmaxf(maxa, fabsf(k));
        D = fmaf(-k, um, D);                 // D *= (1 - k^2)
        #pragma unroll
        for (int i = 0; 2 * i <= m - 2; ++i) {
            int j = m - 2 - i;
            float ui = u[i], uj = u[j];
            if (i < j) {
                u[i] = fmaf(-k, uj, ui);
                u[j] = fmaf(-k, ui, uj);
            } else {
                u[i] = fmaf(-k, ui, ui);
            }
        }
    }
    return fmaxf(maxa, fabsf(u[0] * __fdividef(1.0f, D)));   // k_1
}

// Exact per-row path: true divides, clamp, upward recursion, overwrite row.
__device__ __noinline__ void fixup_row(const float* __restrict__ srow,
                                       float* __restrict__ orow)
{
    float c[M];
    #pragma unroll
    for (int i = 0; i < M; ++i) c[i] = srow[i + 1];

    #pragma unroll
    for (int m = M; m >= 2; --m) {
        float k   = c[m - 1];
        float inv = __fdividef(1.0f, 1.0f - k * k);
        #pragma unroll
        for (int i = 0; 2 * i <= m - 2; ++i) {
            int j = m - 2 - i;
            float ci = c[i], cj = c[j];
            if (i < j) {
                c[i] = fmaf(-k, cj, ci) * inv;
                c[j] = fmaf(-k, ci, cj) * inv;
            } else {
                c[i] = fmaf(-k, ci, ci) * inv;
            }
        }
    }
    #pragma unroll
    for (int i = 0; i < M; ++i)
        c[i] = fminf(fmaxf(c[i], -1.0f), 1.0f);

    #pragma unroll
    for (int m = 2; m <= M; ++m) {
        float km = c[m - 1];
        #pragma unroll
        for (int i = 0; 2 * i <= m - 2; ++i) {
            int j = m - 2 - i;
            float ci = c[i], cj = c[j];
            if (i < j) {
                c[i] = fmaf(km, cj, ci);
                c[j] = fmaf(km, ci, cj);
            } else {
                c[i] = fmaf(km, ci, ci);
            }
        }
    }
    #pragma unroll
    for (int i = 0; i < M; ++i) orow[i + 1] = c[i];
    // orow[0] (gain K) already correct from the bulk copy
}

__global__ __launch_bounds__(THREADS, 4)
void lpc_stability_kernel(const float* __restrict__ in, float* __restrict__ out, int B)
{
    __shared__ float s[WARPS_PER_BLK * WARP_FLOATS];            // 51.2 KB
    __shared__ unsigned long long mbar[WARPS_PER_BLK][2];

    const int wid  = threadIdx.x >> 5;
    const int lane = threadIdx.x & 31;
    const long long wg = (long long)blockIdx.x * WARPS_PER_BLK + wid;
    const long long rbase = wg * ROWS_PER_WARP;
    if (rbase >= B) return;                    // warp-uniform exit
    const int nrows = min((long long)ROWS_PER_WARP, B - rbase);

    float* ws = s + wid * WARP_FLOATS;
    const float* gsrc = in  + rbase * ROW;
    float*       gdst = out + rbase * ROW;
    unsigned s0 = (unsigned)__cvta_generic_to_shared(ws);
    unsigned s1 = s0 + SUB_BYTES;
    unsigned mb0 = (unsigned)__cvta_generic_to_shared(&mbar[wid][0]);
    unsigned mb1 = (unsigned)__cvta_generic_to_shared(&mbar[wid][1]);

    if (nrows == ROWS_PER_WARP) {
        // ---- issue BOTH async loads up front ----
        if (lane == 0) {
            asm volatile("mbarrier.init.shared.b64 [%0], %1;"
                         :: "r"(mb0), "r"(1) : "memory");
            asm volatile("mbarrier.init.shared.b64 [%0], %1;"
                         :: "r"(mb1), "r"(1) : "memory");
            asm volatile("mbarrier.arrive.expect_tx.shared.b64 _, [%0], %1;"
                         :: "r"(mb0), "r"((unsigned)SUB_BYTES) : "memory");
            asm volatile("cp.async.bulk.shared::cluster.global.mbarrier::complete_tx::bytes "
                         "[%0], [%1], %2, [%3];"
                         :: "r"(s0), "l"(gsrc), "r"((unsigned)SUB_BYTES), "r"(mb0)
                         : "memory");
            asm volatile("mbarrier.arrive.expect_tx.shared.b64 _, [%0], %1;"
                         :: "r"(mb1), "r"((unsigned)SUB_BYTES) : "memory");
            asm volatile("cp.async.bulk.shared::cluster.global.mbarrier::complete_tx::bytes "
                         "[%0], [%1], %2, [%3];"
                         :: "r"(s1), "l"(gsrc + SUB_FLOATS), "r"((unsigned)SUB_BYTES), "r"(mb1)
                         : "memory");
        }
        __syncwarp();              // inits visible before other lanes wait

        // ---- sub-span 0: wait, async out-copy, detect ----
        mbar_wait(mb0, 0);
        if (lane == 0) {
            asm volatile("fence.proxy.async.shared::cta;" ::: "memory");
            asm volatile("cp.async.bulk.global.shared::cta.bulk_group [%0], [%1], %2;"
                         :: "l"(gdst), "r"(s0), "r"((unsigned)SUB_BYTES)
                         : "memory");
            asm volatile("cp.async.bulk.commit_group;" ::: "memory");
        }
        const float* rowA = ws + lane * ROW;
        float mA = detector(rowA);             // overlaps load 1 + store 0

        // ---- sub-span 1: wait, async out-copy, detect ----
        mbar_wait(mb1, 0);
        if (lane == 0) {
            asm volatile("fence.proxy.async.shared::cta;" ::: "memory");
            asm volatile("cp.async.bulk.global.shared::cta.bulk_group [%0], [%1], %2;"
                         :: "l"(gdst + SUB_FLOATS), "r"(s1), "r"((unsigned)SUB_BYTES)
                         : "memory");
            asm volatile("cp.async.bulk.commit_group;" ::: "memory");
        }
        const float* rowB = ws + SUB_FLOATS + lane * ROW;
        float mB = detector(rowB);

        // ---- rare path (also catches NaN from degenerate D) ----
        unsigned clip = __ballot_sync(0xffffffffu,
                                      !(mA <= 1.0f) || !(mB <= 1.0f));
        if (clip) {
            if (lane == 0)
                asm volatile("cp.async.bulk.wait_group 0;" ::: "memory");
            __syncwarp();          // fixup STGs ordered after the bulk stores
            if (!(mA <= 1.0f))
                fixup_row(rowA, gdst + (long long)lane * ROW);
            if (!(mB <= 1.0f))
                fixup_row(rowB, gdst + (long long)(SUB_ROWS + lane) * ROW);
        }
    } else {
        // ---- generic tail (not hit for B = 2M): scalar copy + detect ----
        int nelem = nrows * ROW;
        for (int idx = lane; idx < nelem; idx += 32) {
            float v = gsrc[idx];
            gdst[idx] = v;
            ws[idx] = v;
        }
        __syncwarp();
        for (int r = lane; r < nrows; r += 32) {
            const float* row = ws + r * ROW;
            if (!(detector(row) <= 1.0f))
                fixup_row(row, gdst + (long long)r * ROW);
        }
    }
}

extern "C" void kernel_launch(void* const* d_in, const int* in_sizes, int n_in,
                              void* d_out, int out_size)
{
    const float* a = (const float*)d_in[0];
    float* out = (float*)d_out;
    int B = in_sizes[0] / ROW;
    long long nwarps = ((long long)B + ROWS_PER_WARP - 1) / ROWS_PER_WARP;
    int grid = (int)((nwarps + WARPS_PER_BLK - 1) / WARPS_PER_BLK);
    lpc_stability_kernel<<<grid, THREADS>>>(a, out, B);
}